// round 11
// baseline (speedup 1.0000x reference)
#include <cuda_runtime.h>
#include <math.h>

#define NN   100000
#define EE   3200000
#define FIN  256
#define HID  16
#define CC   40
#define FULLM 0xffffffffu

#define SCAN_T 512
#define SCAN_B ((NN + SCAN_T - 1) / SCAN_T)   // 196

// ---------------- scratch (device globals; no allocation allowed) ------------
__device__ int      g_rowptr[NN + 1];
__device__ int      g_fill[NN];
__device__ int      g_rank[EE];
__device__ int      g_col[EE];
__device__ float    g_dinv[NN];
__device__ float4   g_f1[NN * 4];   // x @ W1 (unscaled until k_scale), 16 f/node
__device__ float4   g_f2[NN * 4];   // dinv * relu(h1), 16 floats/node
__device__ unsigned g_flags[SCAN_B];  // decoupled-lookback state: (val<<2)|st

#define FFMA2(d, a, b) asm("fma.rn.f32x2 %0, %1, %2, %0;" : "+l"(d) : "l"(a), "l"(b))
#define PACK2(d, f)    asm("mov.b64 %0, {%1, %1};" : "=l"(d) : "f"(f))
#define UNPACK2(lo, hi, v) asm("mov.b64 {%0, %1}, %2;" : "=f"(lo), "=f"(hi) : "l"(v))

// ---------------- CSR build -------------------------------------------------
// histogram + per-edge within-bucket rank (atomic return value).
// g_fill arrives zeroed (device-global init on first run; k_scan re-zeroes it
// each run after consuming it).
__global__ void k_hist(const int* __restrict__ ei) {
    int i = blockIdx.x * blockDim.x + threadIdx.x;
    if (i < EE / 4) {
        int4 d = ((const int4*)(ei + EE))[i];
        int4 r;
        r.x = atomicAdd(&g_fill[d.x], 1);
        r.y = atomicAdd(&g_fill[d.y], 1);
        r.z = atomicAdd(&g_fill[d.z], 1);
        r.w = atomicAdd(&g_fill[d.w], 1);
        ((int4*)g_rank)[i] = r;
    }
}

// single-pass exclusive scan of g_fill -> g_rowptr, plus dinv. Decoupled lookback.
// Also re-zeroes g_fill for the next replay. g_flags arrives zeroed (k_scatter
// clears it each run).
__global__ void k_scan() {
    __shared__ int wt[SCAN_T / 32];
    __shared__ int s_prefix;
    int tid = threadIdx.x, lane = tid & 31, wid = tid >> 5, b = blockIdx.x;
    int i = b * SCAN_T + tid;
    int v = (i < NN) ? g_fill[i] : 0;

    int x = v;
    #pragma unroll
    for (int off = 1; off < 32; off <<= 1) {
        int t = __shfl_up_sync(FULLM, x, off);
        if (lane >= off) x += t;
    }
    if (lane == 31) wt[wid] = x;
    __syncthreads();
    if (wid == 0) {
        int w = (lane < SCAN_T / 32) ? wt[lane] : 0;
        #pragma unroll
        for (int off = 1; off < SCAN_T / 32; off <<= 1) {
            int t = __shfl_up_sync(FULLM, w, off);
            if (lane >= off) w += t;
        }
        if (lane < SCAN_T / 32) wt[lane] = w;
    }
    __syncthreads();
    int block_tot = wt[SCAN_T / 32 - 1];
    int incl = ((wid == 0) ? 0 : wt[wid - 1]) + x;

    if (tid == 0) {
        unsigned pub = (b == 0) ? (((unsigned)block_tot << 2) | 2u)
                                : (((unsigned)block_tot << 2) | 1u);
        atomicExch(&g_flags[b], pub);
    }

    if (b == 0) {
        if (tid == 0) s_prefix = 0;
    } else if (wid == 0) {
        int prefix = 0;
        int base = b - 1;
        while (true) {
            int idx = base - lane;
            unsigned w = (idx >= 0) ? *((volatile unsigned*)&g_flags[idx]) : 2u;
            unsigned st = w & 3u;
            unsigned pm = __ballot_sync(FULLM, st == 2u);
            unsigned zm = __ballot_sync(FULLM, st == 0u);
            if (pm) {
                int fp = __ffs(pm) - 1;
                if ((zm & ((1u << fp) - 1u)) == 0) {
                    int c = (lane <= fp) ? (int)(w >> 2) : 0;
                    #pragma unroll
                    for (int off = 16; off; off >>= 1)
                        c += __shfl_xor_sync(FULLM, c, off);
                    prefix += c;
                    break;
                }
            } else if (zm == 0) {
                int c = (int)(w >> 2);
                #pragma unroll
                for (int off = 16; off; off >>= 1)
                    c += __shfl_xor_sync(FULLM, c, off);
                prefix += c;
                base -= 32;
            }
        }
        if (lane == 0) {
            s_prefix = prefix;
            atomicExch(&g_flags[b], (((unsigned)(prefix + block_tot)) << 2) | 2u);
        }
    }
    __syncthreads();

    if (i < NN) {
        g_rowptr[i] = s_prefix + incl - v;
        g_dinv[i]   = rsqrtf((float)(v + 1));
        g_fill[i]   = 0;                      // ready for next replay's k_hist
    }
    if (b == SCAN_B - 1 && tid == SCAN_T - 1) g_rowptr[NN] = EE;
}

// scatter with precomputed ranks: no atomics. Also clears g_flags for next run.
__global__ void k_scatter(const int* __restrict__ ei) {
    if (blockIdx.x == 0 && threadIdx.x < SCAN_B) g_flags[threadIdx.x] = 0u;
    int i = blockIdx.x * blockDim.x + threadIdx.x;
    if (i < EE / 4) {
        int4 s = ((const int4*)ei)[i];
        int4 d = ((const int4*)(ei + EE))[i];
        int4 r = ((const int4*)g_rank)[i];
        g_col[g_rowptr[d.x] + r.x] = s.x;
        g_col[g_rowptr[d.y] + r.y] = s.y;
        g_col[g_rowptr[d.z] + r.z] = s.z;
        g_col[g_rowptr[d.w] + r.w] = s.w;
    }
}

// ---------------- layer-1 dense GEMM: g_f1 = x @ W1 (UNSCALED) --------------
// Row-per-thread, x staged through swizzled smem (coalesced LDG, conflict-free
// STS/LDS), W broadcast-LDS. No dependency on dinv -> runs from t=0 on side
// stream, fully hidden under the CSR build.
#define CK 32
__global__ void __launch_bounds__(256) k_gemm1(const float* __restrict__ x,
                                               const float* __restrict__ W1) {
    __shared__ __align__(16) float  Ws[FIN * HID];   // 16 KB, plain row-major
    __shared__ __align__(16) float4 xs[256 * 8];     // 32 KB chunk, swizzled

    int t = threadIdx.x;
    for (int g = t; g < FIN * HID / 4; g += 256)
        ((float4*)Ws)[g] = __ldg(&((const float4*)W1)[g]);

    int rowbase = blockIdx.x * 256;
    int myrow   = rowbase + t;
    bool valid  = myrow < NN;

    unsigned long long acc[8];
    #pragma unroll
    for (int u = 0; u < 8; u++) acc[u] = 0ull;

    int sr = t >> 3;          // staging row (within group of 32)
    int si = t & 7;           // staging float4 slot

    for (int kc = 0; kc < FIN / CK; kc++) {
        __syncthreads();      // xs free (also covers Ws on first iter)
        #pragma unroll
        for (int j = 0; j < 8; j++) {
            int r = sr + j * 32;
            int grow = rowbase + r;
            float4 v = (grow < NN)
                ? __ldg((const float4*)(x + (size_t)grow * FIN + kc * CK) + si)
                : make_float4(0.f, 0.f, 0.f, 0.f);
            xs[r * 8 + ((si + r) & 7)] = v;
        }
        __syncthreads();
        if (valid) {
            #pragma unroll
            for (int i = 0; i < 8; i++) {
                float4 xv = xs[t * 8 + ((i + t) & 7)];
                #pragma unroll
                for (int c = 0; c < 4; c++) {
                    float f = (c == 0) ? xv.x : (c == 1) ? xv.y
                            : (c == 2) ? xv.z : xv.w;
                    unsigned long long xp;
                    PACK2(xp, f);
                    const ulonglong2* wr =
                        (const ulonglong2*)&Ws[(kc * CK + i * 4 + c) * HID];
                    ulonglong2 w0 = wr[0], w1 = wr[1], w2 = wr[2], w3 = wr[3];
                    FFMA2(acc[0], xp, w0.x); FFMA2(acc[1], xp, w0.y);
                    FFMA2(acc[2], xp, w1.x); FFMA2(acc[3], xp, w1.y);
                    FFMA2(acc[4], xp, w2.x); FFMA2(acc[5], xp, w2.y);
                    FFMA2(acc[6], xp, w3.x); FFMA2(acc[7], xp, w3.y);
                }
            }
        }
    }

    if (valid) {
        float r[16];
        #pragma unroll
        for (int u = 0; u < 8; u++)
            UNPACK2(r[2 * u], r[2 * u + 1], acc[u]);
        float4* o = &g_f1[(size_t)myrow * 4];
        o[0] = make_float4(r[0],  r[1],  r[2],  r[3]);
        o[1] = make_float4(r[4],  r[5],  r[6],  r[7]);
        o[2] = make_float4(r[8],  r[9],  r[10], r[11]);
        o[3] = make_float4(r[12], r[13], r[14], r[15]);
    }
}

// apply dinv scaling to g_f1 (runs after k_scan, hidden under k_scatter)
__global__ void k_scale() {
    int i = blockIdx.x * blockDim.x + threadIdx.x;
    if (i < NN * 4) {
        float dv = g_dinv[i >> 2];
        float4 v = g_f1[i];
        v.x *= dv; v.y *= dv; v.z *= dv; v.w *= dv;
        g_f1[i] = v;
    }
}

// -------- shared 16-dim CSR gather: quad-per-edge, float4 loads -------------
__device__ __forceinline__ float4 warp_gather16(const float4* __restrict__ feat,
                                                int node, int lane) {
    int start = g_rowptr[node];
    int cnt   = g_rowptr[node + 1] - start;
    int q     = lane >> 2;
    int fs    = lane & 3;

    float4 acc = make_float4(0.f, 0.f, 0.f, 0.f);
    for (int base = 0; base < cnt; base += 32) {
        int t    = base + lane;
        int cidx = (t < cnt) ? g_col[start + t] : 0;
        int mm   = min(32, cnt - base);
        for (int j = 0; j < mm; j += 8) {
            int src = __shfl_sync(FULLM, cidx, j + q);
            if (j + q < mm) {
                float4 v = feat[(size_t)src * 4 + fs];
                acc.x += v.x; acc.y += v.y; acc.z += v.z; acc.w += v.w;
            }
        }
    }
    #pragma unroll
    for (int off = 4; off <= 16; off <<= 1) {
        acc.x += __shfl_xor_sync(FULLM, acc.x, off);
        acc.y += __shfl_xor_sync(FULLM, acc.y, off);
        acc.z += __shfl_xor_sync(FULLM, acc.z, off);
        acc.w += __shfl_xor_sync(FULLM, acc.w, off);
    }
    float4 sv = feat[(size_t)node * 4 + fs];
    acc.x += sv.x; acc.y += sv.y; acc.z += sv.z; acc.w += sv.w;
    return acc;
}

// -------- layer-1 aggregation + relu: g_f2 = dinv * relu(dinv*agg + b1) -----
__global__ void k_agg1(const float* __restrict__ b1) {
    __shared__ __align__(16) float b1s[HID];
    if (threadIdx.x < HID) b1s[threadIdx.x] = b1[threadIdx.x];
    __syncthreads();

    int lane = threadIdx.x & 31;
    int node = blockIdx.x * (blockDim.x >> 5) + (threadIdx.x >> 5);
    if (node >= NN) return;

    float4 acc = warp_gather16(g_f1, node, lane);

    float dv = g_dinv[node];
    float4 bv = ((const float4*)b1s)[lane & 3];
    float4 h;
    h.x = fmaxf(dv * acc.x + bv.x, 0.f) * dv;
    h.y = fmaxf(dv * acc.y + bv.y, 0.f) * dv;
    h.z = fmaxf(dv * acc.z + bv.z, 0.f) * dv;
    h.w = fmaxf(dv * acc.w + bv.w, 0.f) * dv;

    if (lane < 4) g_f2[(size_t)node * 4 + lane] = h;
}

// -------- layer-2 aggregation + fused 16x40 GEMM + log_softmax --------------
__global__ void k_agg2(const float* __restrict__ W2, const float* __restrict__ b2,
                       float* __restrict__ out) {
    __shared__ float W2s[HID * 64];
    __shared__ float b2s[CC];
    for (int i = threadIdx.x; i < HID * 64; i += blockDim.x) W2s[i] = 0.f;
    __syncthreads();
    for (int i = threadIdx.x; i < HID * CC; i += blockDim.x) {
        int k = i / CC, c = i % CC;
        W2s[k * 64 + c] = W2[i];
    }
    if (threadIdx.x < CC) b2s[threadIdx.x] = b2[threadIdx.x];
    __syncthreads();

    int lane = threadIdx.x & 31;
    int node = blockIdx.x * (blockDim.x >> 5) + (threadIdx.x >> 5);
    if (node >= NN) return;

    float4 acc = warp_gather16(g_f2, node, lane);

    float v0 = 0.f, v1 = 0.f;
    #pragma unroll
    for (int k = 0; k < HID; k++) {
        float comp = ((k & 3) == 0) ? acc.x : ((k & 3) == 1) ? acc.y
                   : ((k & 3) == 2) ? acc.z : acc.w;
        float tk = __shfl_sync(FULLM, comp, k >> 2);
        v0 += tk * W2s[k * 64 + lane];
        v1 += tk * W2s[k * 64 + 32 + lane];
    }

    float dv = g_dinv[node];
    float l0 = dv * v0 + b2s[lane];
    float l1 = (lane < 8) ? (dv * v1 + b2s[32 + lane]) : -3.4e38f;

    float M = fmaxf(l0, l1);
    #pragma unroll
    for (int off = 16; off > 0; off >>= 1)
        M = fmaxf(M, __shfl_xor_sync(FULLM, M, off));

    float se = expf(l0 - M) + ((lane < 8) ? expf(l1 - M) : 0.f);
    #pragma unroll
    for (int off = 16; off > 0; off >>= 1)
        se += __shfl_xor_sync(FULLM, se, off);

    float L = logf(se);
    out[(size_t)node * CC + lane] = l0 - M - L;
    if (lane < 8) out[(size_t)node * CC + 32 + lane] = l1 - M - L;
}

// ---------------- launch ----------------------------------------------------
extern "C" void kernel_launch(void* const* d_in, const int* in_sizes, int n_in,
                              void* d_out, int out_size) {
    const float* x  = (const float*)d_in[0];
    const int*   ei = (const int*)d_in[1];     // int32 edge index
    const float* W1 = (const float*)d_in[2];
    const float* b1 = (const float*)d_in[3];
    const float* W2 = (const float*)d_in[4];
    const float* b2 = (const float*)d_in[5];
    float*       out = (float*)d_out;

    static cudaStream_t s1 = nullptr;
    static cudaEvent_t  ev_fork = nullptr, ev_scan = nullptr, ev_join = nullptr;
    if (!s1) {
        cudaStreamCreateWithFlags(&s1, cudaStreamNonBlocking);
        cudaEventCreateWithFlags(&ev_fork, cudaEventDisableTiming);
        cudaEventCreateWithFlags(&ev_scan, cudaEventDisableTiming);
        cudaEventCreateWithFlags(&ev_join, cudaEventDisableTiming);
    }

    const int E4B = (EE / 4 + 255) / 256;   // 3125
    const int GB  = (NN + 255) / 256;       // 391 blocks of 256 rows
    const int SB  = (NN * 4 + 255) / 256;   // 1563

    // fork immediately: gemm1 has NO dependencies (unscaled output)
    cudaEventRecord(ev_fork, 0);
    cudaStreamWaitEvent(s1, ev_fork, 0);
    k_gemm1<<<GB, 256, 0, s1>>>(x, W1);

    // critical path: CSR build
    k_hist<<<E4B, 256>>>(ei);
    k_scan<<<SCAN_B, SCAN_T>>>();           // rowptr + dinv ready; fill re-zeroed
    cudaEventRecord(ev_scan, 0);

    k_scatter<<<E4B, 256>>>(ei);            // also clears g_flags

    // scale needs scan (dinv) + gemm1; runs on s1 under scatter
    cudaStreamWaitEvent(s1, ev_scan, 0);
    k_scale<<<SB, 256, 0, s1>>>();
    cudaEventRecord(ev_join, s1);

    cudaStreamWaitEvent(0, ev_join, 0);
    k_agg1<<<(NN + 7) / 8, 256>>>(b1);
    k_agg2<<<(NN + 7) / 8, 256>>>(W2, b2, out);
}

// round 12
// speedup vs baseline: 1.3197x; 1.3197x over previous
#include <cuda_runtime.h>
#include <math.h>

#define NN   100000
#define EE   3200000
#define FIN  256
#define HID  16
#define CC   40
#define FULLM 0xffffffffu

#define SCAN_T 512
#define SCAN_B ((NN + SCAN_T - 1) / SCAN_T)   // 196

// ---------------- scratch (device globals; no allocation allowed) ------------
__device__ int      g_rowptr[NN + 1];
__device__ int      g_fill[NN];
__device__ int      g_rank[EE];
__device__ int      g_col[EE];
__device__ float    g_dinv[NN];
__device__ float4   g_f1[NN * 4];   // dinv * (x @ W1), 16 floats/node
__device__ float4   g_f2[NN * 4];   // dinv * relu(h1), 16 floats/node
__device__ unsigned g_flags[SCAN_B];  // decoupled-lookback state: (val<<2)|st

#define FFMA2(d, a, b) asm("fma.rn.f32x2 %0, %1, %2, %0;" : "+l"(d) : "l"(a), "l"(b))
#define PACK2(d, f)    asm("mov.b64 %0, {%1, %1};" : "=l"(d) : "f"(f))
#define UNPACK2(lo, hi, v) asm("mov.b64 {%0, %1}, %2;" : "=f"(lo), "=f"(hi) : "l"(v))

// ---------------- CSR build -------------------------------------------------
// g_fill arrives zeroed (zero-init first run; k_scan re-zeroes each run).
__global__ void k_hist(const int* __restrict__ ei) {
    int i = blockIdx.x * blockDim.x + threadIdx.x;
    if (i < EE / 4) {
        int4 d = ((const int4*)(ei + EE))[i];
        int4 r;
        r.x = atomicAdd(&g_fill[d.x], 1);
        r.y = atomicAdd(&g_fill[d.y], 1);
        r.z = atomicAdd(&g_fill[d.z], 1);
        r.w = atomicAdd(&g_fill[d.w], 1);
        ((int4*)g_rank)[i] = r;
    }
}

// single-pass exclusive scan (decoupled lookback) -> g_rowptr, plus dinv.
// Re-zeroes g_fill. g_flags arrives zeroed (k_scatter clears it each run).
__global__ void k_scan() {
    __shared__ int wt[SCAN_T / 32];
    __shared__ int s_prefix;
    int tid = threadIdx.x, lane = tid & 31, wid = tid >> 5, b = blockIdx.x;
    int i = b * SCAN_T + tid;
    int v = (i < NN) ? g_fill[i] : 0;

    int x = v;
    #pragma unroll
    for (int off = 1; off < 32; off <<= 1) {
        int t = __shfl_up_sync(FULLM, x, off);
        if (lane >= off) x += t;
    }
    if (lane == 31) wt[wid] = x;
    __syncthreads();
    if (wid == 0) {
        int w = (lane < SCAN_T / 32) ? wt[lane] : 0;
        #pragma unroll
        for (int off = 1; off < SCAN_T / 32; off <<= 1) {
            int t = __shfl_up_sync(FULLM, w, off);
            if (lane >= off) w += t;
        }
        if (lane < SCAN_T / 32) wt[lane] = w;
    }
    __syncthreads();
    int block_tot = wt[SCAN_T / 32 - 1];
    int incl = ((wid == 0) ? 0 : wt[wid - 1]) + x;

    if (tid == 0) {
        unsigned pub = (b == 0) ? (((unsigned)block_tot << 2) | 2u)
                                : (((unsigned)block_tot << 2) | 1u);
        atomicExch(&g_flags[b], pub);
    }

    if (b == 0) {
        if (tid == 0) s_prefix = 0;
    } else if (wid == 0) {
        int prefix = 0;
        int base = b - 1;
        while (true) {
            int idx = base - lane;
            unsigned w = (idx >= 0) ? *((volatile unsigned*)&g_flags[idx]) : 2u;
            unsigned st = w & 3u;
            unsigned pm = __ballot_sync(FULLM, st == 2u);
            unsigned zm = __ballot_sync(FULLM, st == 0u);
            if (pm) {
                int fp = __ffs(pm) - 1;
                if ((zm & ((1u << fp) - 1u)) == 0) {
                    int c = (lane <= fp) ? (int)(w >> 2) : 0;
                    #pragma unroll
                    for (int off = 16; off; off >>= 1)
                        c += __shfl_xor_sync(FULLM, c, off);
                    prefix += c;
                    break;
                }
            } else if (zm == 0) {
                int c = (int)(w >> 2);
                #pragma unroll
                for (int off = 16; off; off >>= 1)
                    c += __shfl_xor_sync(FULLM, c, off);
                prefix += c;
                base -= 32;
            }
        }
        if (lane == 0) {
            s_prefix = prefix;
            atomicExch(&g_flags[b], (((unsigned)(prefix + block_tot)) << 2) | 2u);
        }
    }
    __syncthreads();

    if (i < NN) {
        g_rowptr[i] = s_prefix + incl - v;
        g_dinv[i]   = rsqrtf((float)(v + 1));
        g_fill[i]   = 0;                      // ready for next replay's k_hist
    }
    if (b == SCAN_B - 1 && tid == SCAN_T - 1) g_rowptr[NN] = EE;
}

// scatter with precomputed ranks: no atomics. Clears g_flags for next run.
__global__ void k_scatter(const int* __restrict__ ei) {
    if (blockIdx.x == 0 && threadIdx.x < SCAN_B) g_flags[threadIdx.x] = 0u;
    int i = blockIdx.x * blockDim.x + threadIdx.x;
    if (i < EE / 4) {
        int4 s = ((const int4*)ei)[i];
        int4 d = ((const int4*)(ei + EE))[i];
        int4 r = ((const int4*)g_rank)[i];
        g_col[g_rowptr[d.x] + r.x] = s.x;
        g_col[g_rowptr[d.y] + r.y] = s.y;
        g_col[g_rowptr[d.z] + r.z] = s.z;
        g_col[g_rowptr[d.w] + r.w] = s.w;
    }
}

// -------- layer-1 dense GEMM (dinv fused): g_f1 = dinv * (x @ W1) -----------
// Row-per-thread; x staged through swizzled smem (coalesced LDG, conflict-free
// STS/LDS); W broadcast-LDS. Runs on side stream concurrent with k_scatter
// (safe overlap: scatter is store-heavy, not atomic-heavy).
#define CK 32
__global__ void __launch_bounds__(256) k_gemm1(const float* __restrict__ x,
                                               const float* __restrict__ W1) {
    __shared__ __align__(16) float  Ws[FIN * HID];   // 16 KB
    __shared__ __align__(16) float4 xs[256 * 8];     // 32 KB chunk, swizzled

    int t = threadIdx.x;
    for (int g = t; g < FIN * HID / 4; g += 256)
        ((float4*)Ws)[g] = __ldg(&((const float4*)W1)[g]);

    int rowbase = blockIdx.x * 256;
    int myrow   = rowbase + t;
    bool valid  = myrow < NN;

    unsigned long long acc[8];
    #pragma unroll
    for (int u = 0; u < 8; u++) acc[u] = 0ull;

    int sr = t >> 3;          // staging row (within group of 32)
    int si = t & 7;           // staging float4 slot

    for (int kc = 0; kc < FIN / CK; kc++) {
        __syncthreads();
        #pragma unroll
        for (int j = 0; j < 8; j++) {
            int r = sr + j * 32;
            int grow = rowbase + r;
            float4 v = (grow < NN)
                ? __ldg((const float4*)(x + (size_t)grow * FIN + kc * CK) + si)
                : make_float4(0.f, 0.f, 0.f, 0.f);
            xs[r * 8 + ((si + r) & 7)] = v;
        }
        __syncthreads();
        if (valid) {
            #pragma unroll
            for (int i = 0; i < 8; i++) {
                float4 xv = xs[t * 8 + ((i + t) & 7)];
                #pragma unroll
                for (int c = 0; c < 4; c++) {
                    float f = (c == 0) ? xv.x : (c == 1) ? xv.y
                            : (c == 2) ? xv.z : xv.w;
                    unsigned long long xp;
                    PACK2(xp, f);
                    const ulonglong2* wr =
                        (const ulonglong2*)&Ws[(kc * CK + i * 4 + c) * HID];
                    ulonglong2 w0 = wr[0], w1 = wr[1], w2 = wr[2], w3 = wr[3];
                    FFMA2(acc[0], xp, w0.x); FFMA2(acc[1], xp, w0.y);
                    FFMA2(acc[2], xp, w1.x); FFMA2(acc[3], xp, w1.y);
                    FFMA2(acc[4], xp, w2.x); FFMA2(acc[5], xp, w2.y);
                    FFMA2(acc[6], xp, w3.x); FFMA2(acc[7], xp, w3.y);
                }
            }
        }
    }

    if (valid) {
        float r[16];
        #pragma unroll
        for (int u = 0; u < 8; u++)
            UNPACK2(r[2 * u], r[2 * u + 1], acc[u]);
        float dv = g_dinv[myrow];
        float4* o = &g_f1[(size_t)myrow * 4];
        o[0] = make_float4(r[0]*dv,  r[1]*dv,  r[2]*dv,  r[3]*dv);
        o[1] = make_float4(r[4]*dv,  r[5]*dv,  r[6]*dv,  r[7]*dv);
        o[2] = make_float4(r[8]*dv,  r[9]*dv,  r[10]*dv, r[11]*dv);
        o[3] = make_float4(r[12]*dv, r[13]*dv, r[14]*dv, r[15]*dv);
    }
}

// -------- shared 16-dim CSR gather: quad-per-edge, float4 loads -------------
// Full 32-edge chunks run guard-free; single remainder chunk handles the tail.
__device__ __forceinline__ float4 warp_gather16(const float4* __restrict__ feat,
                                                int node, int lane) {
    int start = g_rowptr[node];
    int cnt   = g_rowptr[node + 1] - start;
    int q     = lane >> 2;
    int fs    = lane & 3;
    const int* cp = g_col + start;

    float4 acc = make_float4(0.f, 0.f, 0.f, 0.f);
    int nfull = cnt >> 5;
    for (int c = 0; c < nfull; c++) {
        int cidx = __ldg(cp + c * 32 + lane);
        #pragma unroll
        for (int j = 0; j < 32; j += 8) {
            int src = __shfl_sync(FULLM, cidx, j + q);
            float4 v = __ldg(feat + (size_t)src * 4 + fs);
            acc.x += v.x; acc.y += v.y; acc.z += v.z; acc.w += v.w;
        }
    }
    int rem = cnt & 31;
    if (rem) {
        int base = nfull << 5;
        int cidx = (lane < rem) ? __ldg(cp + base + lane) : 0;
        for (int j = 0; j < rem; j += 8) {
            int src = __shfl_sync(FULLM, cidx, j + q);
            if (j + q < rem) {
                float4 v = __ldg(feat + (size_t)src * 4 + fs);
                acc.x += v.x; acc.y += v.y; acc.z += v.z; acc.w += v.w;
            }
        }
    }
    #pragma unroll
    for (int off = 4; off <= 16; off <<= 1) {
        acc.x += __shfl_xor_sync(FULLM, acc.x, off);
        acc.y += __shfl_xor_sync(FULLM, acc.y, off);
        acc.z += __shfl_xor_sync(FULLM, acc.z, off);
        acc.w += __shfl_xor_sync(FULLM, acc.w, off);
    }
    float4 sv = __ldg(feat + (size_t)node * 4 + fs);      // self loop
    acc.x += sv.x; acc.y += sv.y; acc.z += sv.z; acc.w += sv.w;
    return acc;
}

// -------- layer-1 aggregation + relu: g_f2 = dinv * relu(dinv*agg + b1) -----
__global__ void k_agg1(const float* __restrict__ b1) {
    __shared__ __align__(16) float b1s[HID];
    if (threadIdx.x < HID) b1s[threadIdx.x] = b1[threadIdx.x];
    __syncthreads();

    int lane = threadIdx.x & 31;
    int node = blockIdx.x * (blockDim.x >> 5) + (threadIdx.x >> 5);
    if (node >= NN) return;

    float4 acc = warp_gather16(g_f1, node, lane);

    float dv = g_dinv[node];
    float4 bv = ((const float4*)b1s)[lane & 3];
    float4 h;
    h.x = fmaxf(dv * acc.x + bv.x, 0.f) * dv;
    h.y = fmaxf(dv * acc.y + bv.y, 0.f) * dv;
    h.z = fmaxf(dv * acc.z + bv.z, 0.f) * dv;
    h.w = fmaxf(dv * acc.w + bv.w, 0.f) * dv;

    if (lane < 4) g_f2[(size_t)node * 4 + lane] = h;
}

// -------- layer-2 aggregation + fused 16x40 GEMM + log_softmax --------------
__global__ void k_agg2(const float* __restrict__ W2, const float* __restrict__ b2,
                       float* __restrict__ out) {
    __shared__ float W2s[HID * 64];
    __shared__ float b2s[CC];
    for (int i = threadIdx.x; i < HID * 64; i += blockDim.x) W2s[i] = 0.f;
    __syncthreads();
    for (int i = threadIdx.x; i < HID * CC; i += blockDim.x) {
        int k = i / CC, c = i % CC;
        W2s[k * 64 + c] = W2[i];
    }
    if (threadIdx.x < CC) b2s[threadIdx.x] = b2[threadIdx.x];
    __syncthreads();

    int lane = threadIdx.x & 31;
    int node = blockIdx.x * (blockDim.x >> 5) + (threadIdx.x >> 5);
    if (node >= NN) return;

    float4 acc = warp_gather16(g_f2, node, lane);

    float v0 = 0.f, v1 = 0.f;
    #pragma unroll
    for (int k = 0; k < HID; k++) {
        float comp = ((k & 3) == 0) ? acc.x : ((k & 3) == 1) ? acc.y
                   : ((k & 3) == 2) ? acc.z : acc.w;
        float tk = __shfl_sync(FULLM, comp, k >> 2);
        v0 += tk * W2s[k * 64 + lane];
        v1 += tk * W2s[k * 64 + 32 + lane];
    }

    float dv = g_dinv[node];
    float l0 = dv * v0 + b2s[lane];
    float l1 = (lane < 8) ? (dv * v1 + b2s[32 + lane]) : -3.4e38f;

    float M = fmaxf(l0, l1);
    #pragma unroll
    for (int off = 16; off > 0; off >>= 1)
        M = fmaxf(M, __shfl_xor_sync(FULLM, M, off));

    float se = expf(l0 - M) + ((lane < 8) ? expf(l1 - M) : 0.f);
    #pragma unroll
    for (int off = 16; off > 0; off >>= 1)
        se += __shfl_xor_sync(FULLM, se, off);

    float L = logf(se);
    out[(size_t)node * CC + lane] = l0 - M - L;
    if (lane < 8) out[(size_t)node * CC + 32 + lane] = l1 - M - L;
}

// ---------------- launch ----------------------------------------------------
extern "C" void kernel_launch(void* const* d_in, const int* in_sizes, int n_in,
                              void* d_out, int out_size) {
    const float* x  = (const float*)d_in[0];
    const int*   ei = (const int*)d_in[1];     // int32 edge index
    const float* W1 = (const float*)d_in[2];
    const float* b1 = (const float*)d_in[3];
    const float* W2 = (const float*)d_in[4];
    const float* b2 = (const float*)d_in[5];
    float*       out = (float*)d_out;

    static cudaStream_t s1 = nullptr;
    static cudaEvent_t  ev_fork = nullptr, ev_join = nullptr;
    if (!s1) {
        cudaStreamCreateWithFlags(&s1, cudaStreamNonBlocking);
        cudaEventCreateWithFlags(&ev_fork, cudaEventDisableTiming);
        cudaEventCreateWithFlags(&ev_join, cudaEventDisableTiming);
    }

    const int E4B = (EE / 4 + 255) / 256;   // 3125
    const int GB  = (NN + 255) / 256;       // 391

    // critical path: CSR build
    k_hist<<<E4B, 256>>>(ei);
    k_scan<<<SCAN_B, SCAN_T>>>();           // rowptr + dinv ready; fill re-zeroed

    // fork: gemm1 (needs dinv only) overlaps scatter — the proven-safe slot
    cudaEventRecord(ev_fork, 0);
    cudaStreamWaitEvent(s1, ev_fork, 0);
    k_gemm1<<<GB, 256, 0, s1>>>(x, W1);
    cudaEventRecord(ev_join, s1);

    k_scatter<<<E4B, 256>>>(ei);            // also clears g_flags

    cudaStreamWaitEvent(0, ev_join, 0);
    k_agg1<<<(NN + 7) / 8, 256>>>(b1);
    k_agg2<<<(NN + 7) / 8, 256>>>(W2, b2, out);
}

// round 14
// speedup vs baseline: 1.3341x; 1.0109x over previous
#include <cuda_runtime.h>
#include <math.h>

#define NN   100000
#define EE   3200000
#define FIN  256
#define HID  16
#define CC   40
#define FULLM 0xffffffffu

#define SCAN_T 512
#define SCAN_B ((NN + SCAN_T - 1) / SCAN_T)   // 196

// ---------------- scratch (device globals; no allocation allowed) ------------
__device__ int      g_rowptr[NN + 1];
__device__ int      g_fill[NN];
__device__ int      g_rank[EE];
__device__ int      g_col[EE];
__device__ float    g_dinv[NN];
__device__ float4   g_f1[NN * 4];   // dinv * (x @ W1), 16 floats/node
__device__ float4   g_f2[NN * 4];   // dinv * relu(h1), 16 floats/node
__device__ unsigned g_flags[SCAN_B];  // decoupled-lookback state: (val<<2)|st

#define FFMA2(d, a, b) asm("fma.rn.f32x2 %0, %1, %2, %0;" : "+l"(d) : "l"(a), "l"(b))
#define FADD2(d, a, b) asm("add.rn.f32x2 %0, %1, %2;" : "=l"(d) : "l"(a), "l"(b))
#define PACK2(d, f)    asm("mov.b64 %0, {%1, %1};" : "=l"(d) : "f"(f))
#define UNPACK2(lo, hi, v) asm("mov.b64 {%0, %1}, %2;" : "=f"(lo), "=f"(hi) : "l"(v))

// ---------------- CSR build -------------------------------------------------
// g_fill arrives zeroed (zero-init first run; k_scan re-zeroes each run).
__global__ void k_hist(const int* __restrict__ ei) {
    int i = blockIdx.x * blockDim.x + threadIdx.x;
    if (i < EE / 4) {
        int4 d = ((const int4*)(ei + EE))[i];
        int4 r;
        r.x = atomicAdd(&g_fill[d.x], 1);
        r.y = atomicAdd(&g_fill[d.y], 1);
        r.z = atomicAdd(&g_fill[d.z], 1);
        r.w = atomicAdd(&g_fill[d.w], 1);
        ((int4*)g_rank)[i] = r;
    }
}

// single-pass exclusive scan (decoupled lookback) -> g_rowptr, plus dinv.
// Re-zeroes g_fill. g_flags arrives zeroed (k_scatter clears it each run).
__global__ void k_scan() {
    __shared__ int wt[SCAN_T / 32];
    __shared__ int s_prefix;
    int tid = threadIdx.x, lane = tid & 31, wid = tid >> 5, b = blockIdx.x;
    int i = b * SCAN_T + tid;
    int v = (i < NN) ? g_fill[i] : 0;

    int x = v;
    #pragma unroll
    for (int off = 1; off < 32; off <<= 1) {
        int t = __shfl_up_sync(FULLM, x, off);
        if (lane >= off) x += t;
    }
    if (lane == 31) wt[wid] = x;
    __syncthreads();
    if (wid == 0) {
        int w = (lane < SCAN_T / 32) ? wt[lane] : 0;
        #pragma unroll
        for (int off = 1; off < SCAN_T / 32; off <<= 1) {
            int t = __shfl_up_sync(FULLM, w, off);
            if (lane >= off) w += t;
        }
        if (lane < SCAN_T / 32) wt[lane] = w;
    }
    __syncthreads();
    int block_tot = wt[SCAN_T / 32 - 1];
    int incl = ((wid == 0) ? 0 : wt[wid - 1]) + x;

    if (tid == 0) {
        unsigned pub = (b == 0) ? (((unsigned)block_tot << 2) | 2u)
                                : (((unsigned)block_tot << 2) | 1u);
        atomicExch(&g_flags[b], pub);
    }

    if (b == 0) {
        if (tid == 0) s_prefix = 0;
    } else if (wid == 0) {
        int prefix = 0;
        int base = b - 1;
        while (true) {
            int idx = base - lane;
            unsigned w = (idx >= 0) ? *((volatile unsigned*)&g_flags[idx]) : 2u;
            unsigned st = w & 3u;
            unsigned pm = __ballot_sync(FULLM, st == 2u);
            unsigned zm = __ballot_sync(FULLM, st == 0u);
            if (pm) {
                int fp = __ffs(pm) - 1;
                if ((zm & ((1u << fp) - 1u)) == 0) {
                    int c = (lane <= fp) ? (int)(w >> 2) : 0;
                    #pragma unroll
                    for (int off = 16; off; off >>= 1)
                        c += __shfl_xor_sync(FULLM, c, off);
                    prefix += c;
                    break;
                }
            } else if (zm == 0) {
                int c = (int)(w >> 2);
                #pragma unroll
                for (int off = 16; off; off >>= 1)
                    c += __shfl_xor_sync(FULLM, c, off);
                prefix += c;
                base -= 32;
            }
        }
        if (lane == 0) {
            s_prefix = prefix;
            atomicExch(&g_flags[b], (((unsigned)(prefix + block_tot)) << 2) | 2u);
        }
    }
    __syncthreads();

    if (i < NN) {
        g_rowptr[i] = s_prefix + incl - v;
        g_dinv[i]   = rsqrtf((float)(v + 1));
        g_fill[i]   = 0;                      // ready for next replay's k_hist
    }
    if (b == SCAN_B - 1 && tid == SCAN_T - 1) g_rowptr[NN] = EE;
}

// scatter with precomputed ranks: no atomics. Clears g_flags for next run.
__global__ void k_scatter(const int* __restrict__ ei) {
    if (blockIdx.x == 0 && threadIdx.x < SCAN_B) g_flags[threadIdx.x] = 0u;
    int i = blockIdx.x * blockDim.x + threadIdx.x;
    if (i < EE / 4) {
        int4 s = ((const int4*)ei)[i];
        int4 d = ((const int4*)(ei + EE))[i];
        int4 r = ((const int4*)g_rank)[i];
        g_col[g_rowptr[d.x] + r.x] = s.x;
        g_col[g_rowptr[d.y] + r.y] = s.y;
        g_col[g_rowptr[d.z] + r.z] = s.z;
        g_col[g_rowptr[d.w] + r.w] = s.w;
    }
}

// ---------------- layer-1 dense GEMM: g_f1 = dinv * (x @ W1) ----------------
// D2 column-split warp-cooperative scheme (proven 41.5 us @ R9):
//   lane l -> pair q2 = l>>1, parity p = l&1; lane owns cols [8p,8p+8) and
//   k in {8*q2..+8} u {128+8*q2..+8}. 4 u64 f32x2 accs/row, 4 rows/iter.
//   Coalesced float4 x loads; pair lanes swap via shfl_xor(.,1).
//   W smem swizzle conflict-free per 8-lane phase.
__global__ void __launch_bounds__(128, 5) k_gemm1(const float* __restrict__ x,
                                                  const float* __restrict__ W1) {
    __shared__ __align__(16) float Ws[FIN * HID];          // 16 KB, swizzled
    for (int g = threadIdx.x; g < FIN * HID / 4; g += blockDim.x) {
        int k = g >> 2, ch = g & 3;
        float4 v = __ldg(&((const float4*)W1)[g]);
        unsigned word = ((unsigned)(k * 16) ^ (((unsigned)(k >> 4) & 1u) << 4))
                      + (((unsigned)(ch ^ (k >> 3)) & 3u) << 2);
        *(float4*)&Ws[word] = v;
    }
    __syncthreads();

    int lane = threadIdx.x & 31;
    int gw   = blockIdx.x * 4 + (threadIdx.x >> 5);
    int row0 = gw << 4;                                    // 16 rows per warp
    if (row0 >= NN) return;                                // NN = 6250*16

    int q2 = lane >> 1;
    int p  = lane & 1;
    unsigned sw   = (((unsigned)q2 >> 1) & 1u) << 6;
    unsigned cho0 = (((unsigned)((2 * p)     ^ (q2 & 3))) & 3u) << 4;
    unsigned cho1 = (((unsigned)((2 * p + 1) ^ (q2 & 3))) & 3u) << 4;
    unsigned kbase = (unsigned)q2 << 9;
    int ocol = ((lane & 1) << 3) | (((lane >> 1) & 1) << 2)
             | (((lane >> 2) & 1) << 1) | ((lane >> 3) & 1);

    const char* WsB = (const char*)Ws;

    #pragma unroll 1
    for (int q = 0; q < 4; q++) {
        int ra = row0 + q * 4;
        unsigned long long acc[4][4];
        #pragma unroll
        for (int r = 0; r < 4; r++)
            #pragma unroll
            for (int u = 0; u < 4; u++) acc[r][u] = 0ull;

        #pragma unroll
        for (int j = 0; j < 2; j++) {
            float4 own[4], oth[4];
            #pragma unroll
            for (int r = 0; r < 4; r++)
                own[r] = __ldg((const float4*)(x + (size_t)(ra + r) * FIN + j * 128 + lane * 4));
            #pragma unroll
            for (int r = 0; r < 4; r++) {
                oth[r].x = __shfl_xor_sync(FULLM, own[r].x, 1);
                oth[r].y = __shfl_xor_sync(FULLM, own[r].y, 1);
                oth[r].z = __shfl_xor_sync(FULLM, own[r].z, 1);
                oth[r].w = __shfl_xor_sync(FULLM, own[r].w, 1);
            }
            #pragma unroll
            for (int kk = 0; kk < 8; kk++) {
                unsigned off = (kbase + (unsigned)(j * 8192 + kk * 64)) ^ sw;
                ulonglong2 w0 = *(const ulonglong2*)(WsB + off + cho0);
                ulonglong2 w1 = *(const ulonglong2*)(WsB + off + cho1);
                #pragma unroll
                for (int r = 0; r < 4; r++) {
                    float f;
                    if (kk < 4) {
                        float4 s = p ? oth[r] : own[r];
                        f = (kk == 0) ? s.x : (kk == 1) ? s.y : (kk == 2) ? s.z : s.w;
                    } else {
                        float4 s = p ? own[r] : oth[r];
                        f = (kk == 4) ? s.x : (kk == 5) ? s.y : (kk == 6) ? s.z : s.w;
                    }
                    unsigned long long xp;
                    PACK2(xp, f);
                    FFMA2(acc[r][0], xp, w0.x);
                    FFMA2(acc[r][1], xp, w0.y);
                    FFMA2(acc[r][2], xp, w1.x);
                    FFMA2(acc[r][3], xp, w1.y);
                }
            }
        }

        #pragma unroll
        for (int r = 0; r < 4; r++) {
            unsigned long long h0, h1, P;
            {
                unsigned long long s0 = (lane & 2) ? acc[r][0] : acc[r][2];
                unsigned long long s1 = (lane & 2) ? acc[r][1] : acc[r][3];
                unsigned long long r0 = __shfl_xor_sync(FULLM, s0, 2);
                unsigned long long r1 = __shfl_xor_sync(FULLM, s1, 2);
                unsigned long long k0 = (lane & 2) ? acc[r][2] : acc[r][0];
                unsigned long long k1 = (lane & 2) ? acc[r][3] : acc[r][1];
                FADD2(h0, k0, r0);
                FADD2(h1, k1, r1);
            }
            {
                unsigned long long s = (lane & 4) ? h0 : h1;
                unsigned long long rc = __shfl_xor_sync(FULLM, s, 4);
                unsigned long long kp = (lane & 4) ? h1 : h0;
                FADD2(P, kp, rc);
            }
            float lo, hi;
            UNPACK2(lo, hi, P);
            float snd = (lane & 8) ? lo : hi;
            float rcv = __shfl_xor_sync(FULLM, snd, 8);
            float val = ((lane & 8) ? hi : lo) + rcv;
            val += __shfl_xor_sync(FULLM, val, 16);

            if (lane < 16) {
                float dv = g_dinv[ra + r];
                ((float*)g_f1)[(size_t)(ra + r) * HID + ocol] = val * dv;
            }
        }
    }
}

// -------- shared 16-dim CSR gather: quad-per-edge, float4 loads -------------
// Full 32-edge chunks run guard-free; single remainder chunk handles the tail.
__device__ __forceinline__ float4 warp_gather16(const float4* __restrict__ feat,
                                                int node, int lane) {
    int start = g_rowptr[node];
    int cnt   = g_rowptr[node + 1] - start;
    int q     = lane >> 2;
    int fs    = lane & 3;
    const int* cp = g_col + start;

    float4 acc = make_float4(0.f, 0.f, 0.f, 0.f);
    int nfull = cnt >> 5;
    for (int c = 0; c < nfull; c++) {
        int cidx = __ldg(cp + c * 32 + lane);
        #pragma unroll
        for (int j = 0; j < 32; j += 8) {
            int src = __shfl_sync(FULLM, cidx, j + q);
            float4 v = __ldg(feat + (size_t)src * 4 + fs);
            acc.x += v.x; acc.y += v.y; acc.z += v.z; acc.w += v.w;
        }
    }
    int rem = cnt & 31;
    if (rem) {
        int base = nfull << 5;
        int cidx = (lane < rem) ? __ldg(cp + base + lane) : 0;
        for (int j = 0; j < rem; j += 8) {
            int src = __shfl_sync(FULLM, cidx, j + q);
            if (j + q < rem) {
                float4 v = __ldg(feat + (size_t)src * 4 + fs);
                acc.x += v.x; acc.y += v.y; acc.z += v.z; acc.w += v.w;
            }
        }
    }
    #pragma unroll
    for (int off = 4; off <= 16; off <<= 1) {
        acc.x += __shfl_xor_sync(FULLM, acc.x, off);
        acc.y += __shfl_xor_sync(FULLM, acc.y, off);
        acc.z += __shfl_xor_sync(FULLM, acc.z, off);
        acc.w += __shfl_xor_sync(FULLM, acc.w, off);
    }
    float4 sv = __ldg(feat + (size_t)node * 4 + fs);      // self loop
    acc.x += sv.x; acc.y += sv.y; acc.z += sv.z; acc.w += sv.w;
    return acc;
}

// -------- layer-1 aggregation + relu: g_f2 = dinv * relu(dinv*agg + b1) -----
__global__ void k_agg1(const float* __restrict__ b1) {
    __shared__ __align__(16) float b1s[HID];
    if (threadIdx.x < HID) b1s[threadIdx.x] = b1[threadIdx.x];
    __syncthreads();

    int lane = threadIdx.x & 31;
    int node = blockIdx.x * (blockDim.x >> 5) + (threadIdx.x >> 5);
    if (node >= NN) return;

    float4 acc = warp_gather16(g_f1, node, lane);

    float dv = g_dinv[node];
    float4 bv = ((const float4*)b1s)[lane & 3];
    float4 h;
    h.x = fmaxf(dv * acc.x + bv.x, 0.f) * dv;
    h.y = fmaxf(dv * acc.y + bv.y, 0.f) * dv;
    h.z = fmaxf(dv * acc.z + bv.z, 0.f) * dv;
    h.w = fmaxf(dv * acc.w + bv.w, 0.f) * dv;

    if (lane < 4) g_f2[(size_t)node * 4 + lane] = h;
}

// -------- layer-2 aggregation + fused 16x40 GEMM + log_softmax --------------
__global__ void k_agg2(const float* __restrict__ W2, const float* __restrict__ b2,
                       float* __restrict__ out) {
    __shared__ float W2s[HID * 64];
    __shared__ float b2s[CC];
    for (int i = threadIdx.x; i < HID * 64; i += blockDim.x) W2s[i] = 0.f;
    __syncthreads();
    for (int i = threadIdx.x; i < HID * CC; i += blockDim.x) {
        int k = i / CC, c = i % CC;
        W2s[k * 64 + c] = W2[i];
    }
    if (threadIdx.x < CC) b2s[threadIdx.x] = b2[threadIdx.x];
    __syncthreads();

    int lane = threadIdx.x & 31;
    int node = blockIdx.x * (blockDim.x >> 5) + (threadIdx.x >> 5);
    if (node >= NN) return;

    float4 acc = warp_gather16(g_f2, node, lane);

    float v0 = 0.f, v1 = 0.f;
    #pragma unroll
    for (int k = 0; k < HID; k++) {
        float comp = ((k & 3) == 0) ? acc.x : ((k & 3) == 1) ? acc.y
                   : ((k & 3) == 2) ? acc.z : acc.w;
        float tk = __shfl_sync(FULLM, comp, k >> 2);
        v0 += tk * W2s[k * 64 + lane];
        v1 += tk * W2s[k * 64 + 32 + lane];
    }

    float dv = g_dinv[node];
    float l0 = dv * v0 + b2s[lane];
    float l1 = (lane < 8) ? (dv * v1 + b2s[32 + lane]) : -3.4e38f;

    float M = fmaxf(l0, l1);
    #pragma unroll
    for (int off = 16; off > 0; off >>= 1)
        M = fmaxf(M, __shfl_xor_sync(FULLM, M, off));

    float se = expf(l0 - M) + ((lane < 8) ? expf(l1 - M) : 0.f);
    #pragma unroll
    for (int off = 16; off > 0; off >>= 1)
        se += __shfl_xor_sync(FULLM, se, off);

    float L = logf(se);
    out[(size_t)node * CC + lane] = l0 - M - L;
    if (lane < 8) out[(size_t)node * CC + 32 + lane] = l1 - M - L;
}

// ---------------- launch ----------------------------------------------------
extern "C" void kernel_launch(void* const* d_in, const int* in_sizes, int n_in,
                              void* d_out, int out_size) {
    const float* x  = (const float*)d_in[0];
    const int*   ei = (const int*)d_in[1];     // int32 edge index
    const float* W1 = (const float*)d_in[2];
    const float* b1 = (const float*)d_in[3];
    const float* W2 = (const float*)d_in[4];
    const float* b2 = (const float*)d_in[5];
    float*       out = (float*)d_out;

    static cudaStream_t s1 = nullptr;
    static cudaEvent_t  ev_fork = nullptr, ev_join = nullptr;
    if (!s1) {
        cudaStreamCreateWithFlags(&s1, cudaStreamNonBlocking);
        cudaEventCreateWithFlags(&ev_fork, cudaEventDisableTiming);
        cudaEventCreateWithFlags(&ev_join, cudaEventDisableTiming);
    }

    const int E4B = (EE / 4 + 255) / 256;   // 3125
    const int GB  = (NN / 16 + 3) / 4;      // 1563 blocks, 4 warps x 16 rows

    // critical path: CSR build
    k_hist<<<E4B, 256>>>(ei);
    k_scan<<<SCAN_B, SCAN_T>>>();           // rowptr + dinv ready; fill re-zeroed

    // fork: gemm1 (needs dinv only) overlaps scatter — the proven-safe slot
    cudaEventRecord(ev_fork, 0);
    cudaStreamWaitEvent(s1, ev_fork, 0);
    k_gemm1<<<GB, 128, 0, s1>>>(x, W1);
    cudaEventRecord(ev_join, s1);

    k_scatter<<<E4B, 256>>>(ei);            // also clears g_flags

    cudaStreamWaitEvent(0, ev_join, 0);
    k_agg1<<<(NN + 7) / 8, 256>>>(b1);
    k_agg2<<<(NN + 7) / 8, 256>>>(W2, b2, out);
}

// round 16
// speedup vs baseline: 1.4178x; 1.0628x over previous
#include <cuda_runtime.h>
#include <math.h>

#define NN   100000
#define EE   3200000
#define FIN  256
#define HID  16
#define CC   40
#define FULLM 0xffffffffu

#define SCAN_T 512
#define SCAN_B ((NN + SCAN_T - 1) / SCAN_T)   // 196

// ---------------- scratch (device globals; no allocation allowed) ------------
__device__ int      g_rowptr[NN + 1];
__device__ int      g_fill[NN];
__device__ int      g_rank[EE];
__device__ int      g_col[EE];
__device__ float    g_dinv[NN];
__device__ float4   g_f1[NN * 4];   // dinv * (x @ W1), 16 floats/node
__device__ float4   g_f2[NN * 4];   // dinv * relu(h1), 16 floats/node
__device__ unsigned g_flags[SCAN_B];  // decoupled-lookback state: (val<<2)|st

#define FFMA2(d, a, b) asm("fma.rn.f32x2 %0, %1, %2, %0;" : "+l"(d) : "l"(a), "l"(b))
#define FADD2(d, a, b) asm("add.rn.f32x2 %0, %1, %2;" : "=l"(d) : "l"(a), "l"(b))
#define PACK2(d, f)    asm("mov.b64 %0, {%1, %1};" : "=l"(d) : "f"(f))
#define UNPACK2(lo, hi, v) asm("mov.b64 {%0, %1}, %2;" : "=f"(lo), "=f"(hi) : "l"(v))

// ---------------- CSR build -------------------------------------------------
// g_fill arrives zeroed (zero-init first run; k_scan re-zeroes each run).
__global__ void k_hist(const int* __restrict__ ei) {
    int i = blockIdx.x * blockDim.x + threadIdx.x;
    if (i < EE / 4) {
        int4 d = ((const int4*)(ei + EE))[i];
        int4 r;
        r.x = atomicAdd(&g_fill[d.x], 1);
        r.y = atomicAdd(&g_fill[d.y], 1);
        r.z = atomicAdd(&g_fill[d.z], 1);
        r.w = atomicAdd(&g_fill[d.w], 1);
        ((int4*)g_rank)[i] = r;
    }
}

// single-pass exclusive scan (decoupled lookback) -> g_rowptr, plus dinv.
// Re-zeroes g_fill. g_flags arrives zeroed (k_scatter clears it each run).
__global__ void k_scan() {
    __shared__ int wt[SCAN_T / 32];
    __shared__ int s_prefix;
    int tid = threadIdx.x, lane = tid & 31, wid = tid >> 5, b = blockIdx.x;
    int i = b * SCAN_T + tid;
    int v = (i < NN) ? g_fill[i] : 0;

    int x = v;
    #pragma unroll
    for (int off = 1; off < 32; off <<= 1) {
        int t = __shfl_up_sync(FULLM, x, off);
        if (lane >= off) x += t;
    }
    if (lane == 31) wt[wid] = x;
    __syncthreads();
    if (wid == 0) {
        int w = (lane < SCAN_T / 32) ? wt[lane] : 0;
        #pragma unroll
        for (int off = 1; off < SCAN_T / 32; off <<= 1) {
            int t = __shfl_up_sync(FULLM, w, off);
            if (lane >= off) w += t;
        }
        if (lane < SCAN_T / 32) wt[lane] = w;
    }
    __syncthreads();
    int block_tot = wt[SCAN_T / 32 - 1];
    int incl = ((wid == 0) ? 0 : wt[wid - 1]) + x;

    if (tid == 0) {
        unsigned pub = (b == 0) ? (((unsigned)block_tot << 2) | 2u)
                                : (((unsigned)block_tot << 2) | 1u);
        atomicExch(&g_flags[b], pub);
    }

    if (b == 0) {
        if (tid == 0) s_prefix = 0;
    } else if (wid == 0) {
        int prefix = 0;
        int base = b - 1;
        while (true) {
            int idx = base - lane;
            unsigned w = (idx >= 0) ? *((volatile unsigned*)&g_flags[idx]) : 2u;
            unsigned st = w & 3u;
            unsigned pm = __ballot_sync(FULLM, st == 2u);
            unsigned zm = __ballot_sync(FULLM, st == 0u);
            if (pm) {
                int fp = __ffs(pm) - 1;
                if ((zm & ((1u << fp) - 1u)) == 0) {
                    int c = (lane <= fp) ? (int)(w >> 2) : 0;
                    #pragma unroll
                    for (int off = 16; off; off >>= 1)
                        c += __shfl_xor_sync(FULLM, c, off);
                    prefix += c;
                    break;
                }
            } else if (zm == 0) {
                int c = (int)(w >> 2);
                #pragma unroll
                for (int off = 16; off; off >>= 1)
                    c += __shfl_xor_sync(FULLM, c, off);
                prefix += c;
                base -= 32;
            }
        }
        if (lane == 0) {
            s_prefix = prefix;
            atomicExch(&g_flags[b], (((unsigned)(prefix + block_tot)) << 2) | 2u);
        }
    }
    __syncthreads();

    if (i < NN) {
        g_rowptr[i] = s_prefix + incl - v;
        g_dinv[i]   = rsqrtf((float)(v + 1));
        g_fill[i]   = 0;                      // ready for next replay's k_hist
    }
    if (b == SCAN_B - 1 && tid == SCAN_T - 1) g_rowptr[NN] = EE;
}

// scatter with precomputed ranks: no atomics. Clears g_flags for next run.
__global__ void k_scatter(const int* __restrict__ ei) {
    if (blockIdx.x == 0 && threadIdx.x < SCAN_B) g_flags[threadIdx.x] = 0u;
    int i = blockIdx.x * blockDim.x + threadIdx.x;
    if (i < EE / 4) {
        int4 s = ((const int4*)ei)[i];
        int4 d = ((const int4*)(ei + EE))[i];
        int4 r = ((const int4*)g_rank)[i];
        g_col[g_rowptr[d.x] + r.x] = s.x;
        g_col[g_rowptr[d.y] + r.y] = s.y;
        g_col[g_rowptr[d.z] + r.z] = s.z;
        g_col[g_rowptr[d.w] + r.w] = s.w;
    }
}

// ---------------- layer-1 dense GEMM: g_f1 = dinv * (x @ W1) ----------------
// D2 column-split warp-cooperative scheme (proven @ R9).
__global__ void __launch_bounds__(128, 5) k_gemm1(const float* __restrict__ x,
                                                  const float* __restrict__ W1) {
    __shared__ __align__(16) float Ws[FIN * HID];          // 16 KB, swizzled
    for (int g = threadIdx.x; g < FIN * HID / 4; g += blockDim.x) {
        int k = g >> 2, ch = g & 3;
        float4 v = __ldg(&((const float4*)W1)[g]);
        unsigned word = ((unsigned)(k * 16) ^ (((unsigned)(k >> 4) & 1u) << 4))
                      + (((unsigned)(ch ^ (k >> 3)) & 3u) << 2);
        *(float4*)&Ws[word] = v;
    }
    __syncthreads();

    int lane = threadIdx.x & 31;
    int gw   = blockIdx.x * 4 + (threadIdx.x >> 5);
    int row0 = gw << 4;                                    // 16 rows per warp
    if (row0 >= NN) return;                                // NN = 6250*16

    int q2 = lane >> 1;
    int p  = lane & 1;
    unsigned sw   = (((unsigned)q2 >> 1) & 1u) << 6;
    unsigned cho0 = (((unsigned)((2 * p)     ^ (q2 & 3))) & 3u) << 4;
    unsigned cho1 = (((unsigned)((2 * p + 1) ^ (q2 & 3))) & 3u) << 4;
    unsigned kbase = (unsigned)q2 << 9;
    int ocol = ((lane & 1) << 3) | (((lane >> 1) & 1) << 2)
             | (((lane >> 2) & 1) << 1) | ((lane >> 3) & 1);

    const char* WsB = (const char*)Ws;

    #pragma unroll 1
    for (int q = 0; q < 4; q++) {
        int ra = row0 + q * 4;
        unsigned long long acc[4][4];
        #pragma unroll
        for (int r = 0; r < 4; r++)
            #pragma unroll
            for (int u = 0; u < 4; u++) acc[r][u] = 0ull;

        #pragma unroll
        for (int j = 0; j < 2; j++) {
            float4 own[4], oth[4];
            #pragma unroll
            for (int r = 0; r < 4; r++)
                own[r] = __ldg((const float4*)(x + (size_t)(ra + r) * FIN + j * 128 + lane * 4));
            #pragma unroll
            for (int r = 0; r < 4; r++) {
                oth[r].x = __shfl_xor_sync(FULLM, own[r].x, 1);
                oth[r].y = __shfl_xor_sync(FULLM, own[r].y, 1);
                oth[r].z = __shfl_xor_sync(FULLM, own[r].z, 1);
                oth[r].w = __shfl_xor_sync(FULLM, own[r].w, 1);
            }
            #pragma unroll
            for (int kk = 0; kk < 8; kk++) {
                unsigned off = (kbase + (unsigned)(j * 8192 + kk * 64)) ^ sw;
                ulonglong2 w0 = *(const ulonglong2*)(WsB + off + cho0);
                ulonglong2 w1 = *(const ulonglong2*)(WsB + off + cho1);
                #pragma unroll
                for (int r = 0; r < 4; r++) {
                    float f;
                    if (kk < 4) {
                        float4 s = p ? oth[r] : own[r];
                        f = (kk == 0) ? s.x : (kk == 1) ? s.y : (kk == 2) ? s.z : s.w;
                    } else {
                        float4 s = p ? own[r] : oth[r];
                        f = (kk == 4) ? s.x : (kk == 5) ? s.y : (kk == 6) ? s.z : s.w;
                    }
                    unsigned long long xp;
                    PACK2(xp, f);
                    FFMA2(acc[r][0], xp, w0.x);
                    FFMA2(acc[r][1], xp, w0.y);
                    FFMA2(acc[r][2], xp, w1.x);
                    FFMA2(acc[r][3], xp, w1.y);
                }
            }
        }

        #pragma unroll
        for (int r = 0; r < 4; r++) {
            unsigned long long h0, h1, P;
            {
                unsigned long long s0 = (lane & 2) ? acc[r][0] : acc[r][2];
                unsigned long long s1 = (lane & 2) ? acc[r][1] : acc[r][3];
                unsigned long long r0 = __shfl_xor_sync(FULLM, s0, 2);
                unsigned long long r1 = __shfl_xor_sync(FULLM, s1, 2);
                unsigned long long k0 = (lane & 2) ? acc[r][2] : acc[r][0];
                unsigned long long k1 = (lane & 2) ? acc[r][3] : acc[r][1];
                FADD2(h0, k0, r0);
                FADD2(h1, k1, r1);
            }
            {
                unsigned long long s = (lane & 4) ? h0 : h1;
                unsigned long long rc = __shfl_xor_sync(FULLM, s, 4);
                unsigned long long kp = (lane & 4) ? h1 : h0;
                FADD2(P, kp, rc);
            }
            float lo, hi;
            UNPACK2(lo, hi, P);
            float snd = (lane & 8) ? lo : hi;
            float rcv = __shfl_xor_sync(FULLM, snd, 8);
            float val = ((lane & 8) ? hi : lo) + rcv;
            val += __shfl_xor_sync(FULLM, val, 16);

            if (lane < 16) {
                float dv = g_dinv[ra + r];
                ((float*)g_f1)[(size_t)(ra + r) * HID + ocol] = val * dv;
            }
        }
    }
}

// -------- shared 16-dim CSR gather (R9-exact form) --------------------------
// Serial shfl->ldg->add chain: low MLP_p1 keeps cross-CTA L1tex-queue
// contention (spread) down — measured faster than the batched/unrolled form.
__device__ __forceinline__ float4 warp_gather16(const float4* __restrict__ feat,
                                                int node, int lane) {
    int start = g_rowptr[node];
    int cnt   = g_rowptr[node + 1] - start;
    int q     = lane >> 2;
    int fs    = lane & 3;

    float4 acc = make_float4(0.f, 0.f, 0.f, 0.f);
    for (int base = 0; base < cnt; base += 32) {
        int t    = base + lane;
        int cidx = (t < cnt) ? g_col[start + t] : 0;
        int mm   = min(32, cnt - base);
        for (int j = 0; j < mm; j += 8) {
            int src = __shfl_sync(FULLM, cidx, j + q);
            if (j + q < mm) {
                float4 v = feat[(size_t)src * 4 + fs];
                acc.x += v.x; acc.y += v.y; acc.z += v.z; acc.w += v.w;
            }
        }
    }
    #pragma unroll
    for (int off = 4; off <= 16; off <<= 1) {
        acc.x += __shfl_xor_sync(FULLM, acc.x, off);
        acc.y += __shfl_xor_sync(FULLM, acc.y, off);
        acc.z += __shfl_xor_sync(FULLM, acc.z, off);
        acc.w += __shfl_xor_sync(FULLM, acc.w, off);
    }
    float4 sv = feat[(size_t)node * 4 + fs];              // self loop
    acc.x += sv.x; acc.y += sv.y; acc.z += sv.z; acc.w += sv.w;
    return acc;
}

// -------- layer-1 aggregation + relu: g_f2 = dinv * relu(dinv*agg + b1) -----
__global__ void k_agg1(const float* __restrict__ b1) {
    __shared__ __align__(16) float b1s[HID];
    if (threadIdx.x < HID) b1s[threadIdx.x] = b1[threadIdx.x];
    __syncthreads();

    int lane = threadIdx.x & 31;
    int node = blockIdx.x * (blockDim.x >> 5) + (threadIdx.x >> 5);
    if (node >= NN) return;

    float4 acc = warp_gather16(g_f1, node, lane);

    float dv = g_dinv[node];
    float4 bv = ((const float4*)b1s)[lane & 3];
    float4 h;
    h.x = fmaxf(dv * acc.x + bv.x, 0.f) * dv;
    h.y = fmaxf(dv * acc.y + bv.y, 0.f) * dv;
    h.z = fmaxf(dv * acc.z + bv.z, 0.f) * dv;
    h.w = fmaxf(dv * acc.w + bv.w, 0.f) * dv;

    if (lane < 4) g_f2[(size_t)node * 4 + lane] = h;
}

// -------- layer-2 aggregation + fused 16x40 GEMM + log_softmax --------------
__global__ void k_agg2(const float* __restrict__ W2, const float* __restrict__ b2,
                       float* __restrict__ out) {
    __shared__ float W2s[HID * 64];
    __shared__ float b2s[CC];
    for (int i = threadIdx.x; i < HID * 64; i += blockDim.x) W2s[i] = 0.f;
    __syncthreads();
    for (int i = threadIdx.x; i < HID * CC; i += blockDim.x) {
        int k = i / CC, c = i % CC;
        W2s[k * 64 + c] = W2[i];
    }
    if (threadIdx.x < CC) b2s[threadIdx.x] = b2[threadIdx.x];
    __syncthreads();

    int lane = threadIdx.x & 31;
    int node = blockIdx.x * (blockDim.x >> 5) + (threadIdx.x >> 5);
    if (node >= NN) return;

    float4 acc = warp_gather16(g_f2, node, lane);

    float v0 = 0.f, v1 = 0.f;
    #pragma unroll
    for (int k = 0; k < HID; k++) {
        float comp = ((k & 3) == 0) ? acc.x : ((k & 3) == 1) ? acc.y
                   : ((k & 3) == 2) ? acc.z : acc.w;
        float tk = __shfl_sync(FULLM, comp, k >> 2);
        v0 += tk * W2s[k * 64 + lane];
        v1 += tk * W2s[k * 64 + 32 + lane];
    }

    float dv = g_dinv[node];
    float l0 = dv * v0 + b2s[lane];
    float l1 = (lane < 8) ? (dv * v1 + b2s[32 + lane]) : -3.4e38f;

    float M = fmaxf(l0, l1);
    #pragma unroll
    for (int off = 16; off > 0; off >>= 1)
        M = fmaxf(M, __shfl_xor_sync(FULLM, M, off));

    float se = expf(l0 - M) + ((lane < 8) ? expf(l1 - M) : 0.f);
    #pragma unroll
    for (int off = 16; off > 0; off >>= 1)
        se += __shfl_xor_sync(FULLM, se, off);

    float L = logf(se);
    out[(size_t)node * CC + lane] = l0 - M - L;
    if (lane < 8) out[(size_t)node * CC + 32 + lane] = l1 - M - L;
}

// ---------------- launch ----------------------------------------------------
extern "C" void kernel_launch(void* const* d_in, const int* in_sizes, int n_in,
                              void* d_out, int out_size) {
    const float* x  = (const float*)d_in[0];
    const int*   ei = (const int*)d_in[1];     // int32 edge index
    const float* W1 = (const float*)d_in[2];
    const float* b1 = (const float*)d_in[3];
    const float* W2 = (const float*)d_in[4];
    const float* b2 = (const float*)d_in[5];
    float*       out = (float*)d_out;

    static cudaStream_t s1 = nullptr;
    static cudaEvent_t  ev_fork = nullptr, ev_join = nullptr;
    if (!s1) {
        cudaStreamCreateWithFlags(&s1, cudaStreamNonBlocking);
        cudaEventCreateWithFlags(&ev_fork, cudaEventDisableTiming);
        cudaEventCreateWithFlags(&ev_join, cudaEventDisableTiming);
    }

    const int E4B = (EE / 4 + 255) / 256;   // 3125
    const int GB  = (NN / 16 + 3) / 4;      // 1563 blocks, 4 warps x 16 rows

    // critical path: CSR build
    k_hist<<<E4B, 256>>>(ei);
    k_scan<<<SCAN_B, SCAN_T>>>();           // rowptr + dinv ready; fill re-zeroed

    // fork: gemm1 (needs dinv only) overlaps scatter — the proven-safe slot
    cudaEventRecord(ev_fork, 0);
    cudaStreamWaitEvent(s1, ev_fork, 0);
    k_gemm1<<<GB, 128, 0, s1>>>(x, W1);
    cudaEventRecord(ev_join, s1);

    k_scatter<<<E4B, 256>>>(ei);            // also clears g_flags

    cudaStreamWaitEvent(0, ev_join, 0);
    k_agg1<<<(NN + 7) / 8, 256>>>(b1);
    k_agg2<<<(NN + 7) / 8, 256>>>(W2, b2, out);
}

// round 17
// speedup vs baseline: 1.4305x; 1.0089x over previous
#include <cuda_runtime.h>
#include <math.h>

#define NN   100000
#define EE   3200000
#define FIN  256
#define HID  16
#define CC   40
#define FULLM 0xffffffffu

#define SCAN_T 512
#define SCAN_B ((NN + SCAN_T - 1) / SCAN_T)   // 196

// ---------------- scratch (device globals; no allocation allowed) ------------
__device__ int      g_rowptr[NN + 1];
__device__ int      g_fill[NN];
__device__ int      g_rank[EE];
__device__ int      g_col[EE];
__device__ float    g_dinv[NN];
__device__ float4   g_f1[NN * 4];   // dinv * (x @ W1), 16 floats/node
__device__ float4   g_f2[NN * 4];   // dinv * relu(h1), 16 floats/node
__device__ unsigned g_flags[SCAN_B];  // decoupled-lookback state: (val<<2)|st

#define FFMA2(d, a, b) asm("fma.rn.f32x2 %0, %1, %2, %0;" : "+l"(d) : "l"(a), "l"(b))
#define FADD2(d, a, b) asm("add.rn.f32x2 %0, %1, %2;" : "=l"(d) : "l"(a), "l"(b))
#define PACK2(d, f)    asm("mov.b64 %0, {%1, %1};" : "=l"(d) : "f"(f))
#define UNPACK2(lo, hi, v) asm("mov.b64 {%0, %1}, %2;" : "=f"(lo), "=f"(hi) : "l"(v))

// ---------------- CSR build -------------------------------------------------
// g_fill arrives zeroed (zero-init first run; k_agg2 re-zeroes each run).
__global__ void k_hist(const int* __restrict__ ei) {
    int i = blockIdx.x * blockDim.x + threadIdx.x;
    if (i < EE / 4) {
        int4 d = ((const int4*)(ei + EE))[i];
        int4 r;
        r.x = atomicAdd(&g_fill[d.x], 1);
        r.y = atomicAdd(&g_fill[d.y], 1);
        r.z = atomicAdd(&g_fill[d.z], 1);
        r.w = atomicAdd(&g_fill[d.w], 1);
        ((int4*)g_rank)[i] = r;
    }
}

// single-pass exclusive scan (decoupled lookback) -> g_rowptr, plus dinv.
// Does NOT zero g_fill (k_gemm1's epilogue reads it concurrently; k_agg2
// zeroes it). g_flags arrives zeroed (k_scatter clears it each run).
__global__ void k_scan() {
    __shared__ int wt[SCAN_T / 32];
    __shared__ int s_prefix;
    int tid = threadIdx.x, lane = tid & 31, wid = tid >> 5, b = blockIdx.x;
    int i = b * SCAN_T + tid;
    int v = (i < NN) ? g_fill[i] : 0;

    int x = v;
    #pragma unroll
    for (int off = 1; off < 32; off <<= 1) {
        int t = __shfl_up_sync(FULLM, x, off);
        if (lane >= off) x += t;
    }
    if (lane == 31) wt[wid] = x;
    __syncthreads();
    if (wid == 0) {
        int w = (lane < SCAN_T / 32) ? wt[lane] : 0;
        #pragma unroll
        for (int off = 1; off < SCAN_T / 32; off <<= 1) {
            int t = __shfl_up_sync(FULLM, w, off);
            if (lane >= off) w += t;
        }
        if (lane < SCAN_T / 32) wt[lane] = w;
    }
    __syncthreads();
    int block_tot = wt[SCAN_T / 32 - 1];
    int incl = ((wid == 0) ? 0 : wt[wid - 1]) + x;

    if (tid == 0) {
        unsigned pub = (b == 0) ? (((unsigned)block_tot << 2) | 2u)
                                : (((unsigned)block_tot << 2) | 1u);
        atomicExch(&g_flags[b], pub);
    }

    if (b == 0) {
        if (tid == 0) s_prefix = 0;
    } else if (wid == 0) {
        int prefix = 0;
        int base = b - 1;
        while (true) {
            int idx = base - lane;
            unsigned w = (idx >= 0) ? *((volatile unsigned*)&g_flags[idx]) : 2u;
            unsigned st = w & 3u;
            unsigned pm = __ballot_sync(FULLM, st == 2u);
            unsigned zm = __ballot_sync(FULLM, st == 0u);
            if (pm) {
                int fp = __ffs(pm) - 1;
                if ((zm & ((1u << fp) - 1u)) == 0) {
                    int c = (lane <= fp) ? (int)(w >> 2) : 0;
                    #pragma unroll
                    for (int off = 16; off; off >>= 1)
                        c += __shfl_xor_sync(FULLM, c, off);
                    prefix += c;
                    break;
                }
            } else if (zm == 0) {
                int c = (int)(w >> 2);
                #pragma unroll
                for (int off = 16; off; off >>= 1)
                    c += __shfl_xor_sync(FULLM, c, off);
                prefix += c;
                base -= 32;
            }
        }
        if (lane == 0) {
            s_prefix = prefix;
            atomicExch(&g_flags[b], (((unsigned)(prefix + block_tot)) << 2) | 2u);
        }
    }
    __syncthreads();

    if (i < NN) {
        g_rowptr[i] = s_prefix + incl - v;
        g_dinv[i]   = rsqrtf((float)(v + 1));
    }
    if (b == SCAN_B - 1 && tid == SCAN_T - 1) g_rowptr[NN] = EE;
}

// scatter with precomputed ranks: no atomics. Clears g_flags for next run.
__global__ void k_scatter(const int* __restrict__ ei) {
    if (blockIdx.x == 0 && threadIdx.x < SCAN_B) g_flags[threadIdx.x] = 0u;
    int i = blockIdx.x * blockDim.x + threadIdx.x;
    if (i < EE / 4) {
        int4 s = ((const int4*)ei)[i];
        int4 d = ((const int4*)(ei + EE))[i];
        int4 r = ((const int4*)g_rank)[i];
        g_col[g_rowptr[d.x] + r.x] = s.x;
        g_col[g_rowptr[d.y] + r.y] = s.y;
        g_col[g_rowptr[d.z] + r.z] = s.z;
        g_col[g_rowptr[d.w] + r.w] = s.w;
    }
}

// ---------------- layer-1 dense GEMM: g_f1 = dinv * (x @ W1) ----------------
// D2 column-split warp-cooperative scheme (proven @ R9). Forked right after
// k_hist: the epilogue derives dinv from the finished histogram
// (dv = rsqrt(g_fill[row]+1)), so there is NO dependency on k_scan and the
// kernel overlaps scan + scatter on the side stream.
__global__ void __launch_bounds__(128, 5) k_gemm1(const float* __restrict__ x,
                                                  const float* __restrict__ W1) {
    __shared__ __align__(16) float Ws[FIN * HID];          // 16 KB, swizzled
    for (int g = threadIdx.x; g < FIN * HID / 4; g += blockDim.x) {
        int k = g >> 2, ch = g & 3;
        float4 v = __ldg(&((const float4*)W1)[g]);
        unsigned word = ((unsigned)(k * 16) ^ (((unsigned)(k >> 4) & 1u) << 4))
                      + (((unsigned)(ch ^ (k >> 3)) & 3u) << 2);
        *(float4*)&Ws[word] = v;
    }
    __syncthreads();

    int lane = threadIdx.x & 31;
    int gw   = blockIdx.x * 4 + (threadIdx.x >> 5);
    int row0 = gw << 4;                                    // 16 rows per warp
    if (row0 >= NN) return;                                // NN = 6250*16

    int q2 = lane >> 1;
    int p  = lane & 1;
    unsigned sw   = (((unsigned)q2 >> 1) & 1u) << 6;
    unsigned cho0 = (((unsigned)((2 * p)     ^ (q2 & 3))) & 3u) << 4;
    unsigned cho1 = (((unsigned)((2 * p + 1) ^ (q2 & 3))) & 3u) << 4;
    unsigned kbase = (unsigned)q2 << 9;
    int ocol = ((lane & 1) << 3) | (((lane >> 1) & 1) << 2)
             | (((lane >> 2) & 1) << 1) | ((lane >> 3) & 1);

    const char* WsB = (const char*)Ws;

    #pragma unroll 1
    for (int q = 0; q < 4; q++) {
        int ra = row0 + q * 4;
        unsigned long long acc[4][4];
        #pragma unroll
        for (int r = 0; r < 4; r++)
            #pragma unroll
            for (int u = 0; u < 4; u++) acc[r][u] = 0ull;

        #pragma unroll
        for (int j = 0; j < 2; j++) {
            float4 own[4], oth[4];
            #pragma unroll
            for (int r = 0; r < 4; r++)
                own[r] = __ldg((const float4*)(x + (size_t)(ra + r) * FIN + j * 128 + lane * 4));
            #pragma unroll
            for (int r = 0; r < 4; r++) {
                oth[r].x = __shfl_xor_sync(FULLM, own[r].x, 1);
                oth[r].y = __shfl_xor_sync(FULLM, own[r].y, 1);
                oth[r].z = __shfl_xor_sync(FULLM, own[r].z, 1);
                oth[r].w = __shfl_xor_sync(FULLM, own[r].w, 1);
            }
            #pragma unroll
            for (int kk = 0; kk < 8; kk++) {
                unsigned off = (kbase + (unsigned)(j * 8192 + kk * 64)) ^ sw;
                ulonglong2 w0 = *(const ulonglong2*)(WsB + off + cho0);
                ulonglong2 w1 = *(const ulonglong2*)(WsB + off + cho1);
                #pragma unroll
                for (int r = 0; r < 4; r++) {
                    float f;
                    if (kk < 4) {
                        float4 s = p ? oth[r] : own[r];
                        f = (kk == 0) ? s.x : (kk == 1) ? s.y : (kk == 2) ? s.z : s.w;
                    } else {
                        float4 s = p ? own[r] : oth[r];
                        f = (kk == 4) ? s.x : (kk == 5) ? s.y : (kk == 6) ? s.z : s.w;
                    }
                    unsigned long long xp;
                    PACK2(xp, f);
                    FFMA2(acc[r][0], xp, w0.x);
                    FFMA2(acc[r][1], xp, w0.y);
                    FFMA2(acc[r][2], xp, w1.x);
                    FFMA2(acc[r][3], xp, w1.y);
                }
            }
        }

        #pragma unroll
        for (int r = 0; r < 4; r++) {
            unsigned long long h0, h1, P;
            {
                unsigned long long s0 = (lane & 2) ? acc[r][0] : acc[r][2];
                unsigned long long s1 = (lane & 2) ? acc[r][1] : acc[r][3];
                unsigned long long r0 = __shfl_xor_sync(FULLM, s0, 2);
                unsigned long long r1 = __shfl_xor_sync(FULLM, s1, 2);
                unsigned long long k0 = (lane & 2) ? acc[r][2] : acc[r][0];
                unsigned long long k1 = (lane & 2) ? acc[r][3] : acc[r][1];
                FADD2(h0, k0, r0);
                FADD2(h1, k1, r1);
            }
            {
                unsigned long long s = (lane & 4) ? h0 : h1;
                unsigned long long rc = __shfl_xor_sync(FULLM, s, 4);
                unsigned long long kp = (lane & 4) ? h1 : h0;
                FADD2(P, kp, rc);
            }
            float lo, hi;
            UNPACK2(lo, hi, P);
            float snd = (lane & 8) ? lo : hi;
            float rcv = __shfl_xor_sync(FULLM, snd, 8);
            float val = ((lane & 8) ? hi : lo) + rcv;
            val += __shfl_xor_sync(FULLM, val, 16);

            if (lane < 16) {
                // dinv straight from the histogram — no k_scan dependency
                float dv = rsqrtf((float)g_fill[ra + r] + 1.0f);
                ((float*)g_f1)[(size_t)(ra + r) * HID + ocol] = val * dv;
            }
        }
    }
}

// -------- shared 16-dim CSR gather (R9-exact form) --------------------------
// Serial shfl->ldg->add chain: low MLP_p1 keeps cross-CTA L1tex-queue
// contention (spread) down — measured faster than the batched/unrolled form.
__device__ __forceinline__ float4 warp_gather16(const float4* __restrict__ feat,
                                                int node, int lane) {
    int start = g_rowptr[node];
    int cnt   = g_rowptr[node + 1] - start;
    int q     = lane >> 2;
    int fs    = lane & 3;

    float4 acc = make_float4(0.f, 0.f, 0.f, 0.f);
    for (int base = 0; base < cnt; base += 32) {
        int t    = base + lane;
        int cidx = (t < cnt) ? g_col[start + t] : 0;
        int mm   = min(32, cnt - base);
        for (int j = 0; j < mm; j += 8) {
            int src = __shfl_sync(FULLM, cidx, j + q);
            if (j + q < mm) {
                float4 v = feat[(size_t)src * 4 + fs];
                acc.x += v.x; acc.y += v.y; acc.z += v.z; acc.w += v.w;
            }
        }
    }
    #pragma unroll
    for (int off = 4; off <= 16; off <<= 1) {
        acc.x += __shfl_xor_sync(FULLM, acc.x, off);
        acc.y += __shfl_xor_sync(FULLM, acc.y, off);
        acc.z += __shfl_xor_sync(FULLM, acc.z, off);
        acc.w += __shfl_xor_sync(FULLM, acc.w, off);
    }
    float4 sv = feat[(size_t)node * 4 + fs];              // self loop
    acc.x += sv.x; acc.y += sv.y; acc.z += sv.z; acc.w += sv.w;
    return acc;
}

// -------- layer-1 aggregation + relu: g_f2 = dinv * relu(dinv*agg + b1) -----
__global__ void k_agg1(const float* __restrict__ b1) {
    __shared__ __align__(16) float b1s[HID];
    if (threadIdx.x < HID) b1s[threadIdx.x] = b1[threadIdx.x];
    __syncthreads();

    int lane = threadIdx.x & 31;
    int node = blockIdx.x * (blockDim.x >> 5) + (threadIdx.x >> 5);
    if (node >= NN) return;

    float4 acc = warp_gather16(g_f1, node, lane);

    float dv = g_dinv[node];
    float4 bv = ((const float4*)b1s)[lane & 3];
    float4 h;
    h.x = fmaxf(dv * acc.x + bv.x, 0.f) * dv;
    h.y = fmaxf(dv * acc.y + bv.y, 0.f) * dv;
    h.z = fmaxf(dv * acc.z + bv.z, 0.f) * dv;
    h.w = fmaxf(dv * acc.w + bv.w, 0.f) * dv;

    if (lane < 4) g_f2[(size_t)node * 4 + lane] = h;
}

// -------- layer-2 aggregation + fused 16x40 GEMM + log_softmax --------------
// Also re-zeroes g_fill for the next replay (safe: runs strictly after
// k_gemm1's epilogue has consumed it).
__global__ void k_agg2(const float* __restrict__ W2, const float* __restrict__ b2,
                       float* __restrict__ out) {
    __shared__ float W2s[HID * 64];
    __shared__ float b2s[CC];
    int gi = blockIdx.x * blockDim.x + threadIdx.x;
    if (gi < NN) g_fill[gi] = 0;
    for (int i = threadIdx.x; i < HID * 64; i += blockDim.x) W2s[i] = 0.f;
    __syncthreads();
    for (int i = threadIdx.x; i < HID * CC; i += blockDim.x) {
        int k = i / CC, c = i % CC;
        W2s[k * 64 + c] = W2[i];
    }
    if (threadIdx.x < CC) b2s[threadIdx.x] = b2[threadIdx.x];
    __syncthreads();

    int lane = threadIdx.x & 31;
    int node = blockIdx.x * (blockDim.x >> 5) + (threadIdx.x >> 5);
    if (node >= NN) return;

    float4 acc = warp_gather16(g_f2, node, lane);

    float v0 = 0.f, v1 = 0.f;
    #pragma unroll
    for (int k = 0; k < HID; k++) {
        float comp = ((k & 3) == 0) ? acc.x : ((k & 3) == 1) ? acc.y
                   : ((k & 3) == 2) ? acc.z : acc.w;
        float tk = __shfl_sync(FULLM, comp, k >> 2);
        v0 += tk * W2s[k * 64 + lane];
        v1 += tk * W2s[k * 64 + 32 + lane];
    }

    float dv = g_dinv[node];
    float l0 = dv * v0 + b2s[lane];
    float l1 = (lane < 8) ? (dv * v1 + b2s[32 + lane]) : -3.4e38f;

    float M = fmaxf(l0, l1);
    #pragma unroll
    for (int off = 16; off > 0; off >>= 1)
        M = fmaxf(M, __shfl_xor_sync(FULLM, M, off));

    float se = expf(l0 - M) + ((lane < 8) ? expf(l1 - M) : 0.f);
    #pragma unroll
    for (int off = 16; off > 0; off >>= 1)
        se += __shfl_xor_sync(FULLM, se, off);

    float L = logf(se);
    out[(size_t)node * CC + lane] = l0 - M - L;
    if (lane < 8) out[(size_t)node * CC + 32 + lane] = l1 - M - L;
}

// ---------------- launch ----------------------------------------------------
extern "C" void kernel_launch(void* const* d_in, const int* in_sizes, int n_in,
                              void* d_out, int out_size) {
    const float* x  = (const float*)d_in[0];
    const int*   ei = (const int*)d_in[1];     // int32 edge index
    const float* W1 = (const float*)d_in[2];
    const float* b1 = (const float*)d_in[3];
    const float* W2 = (const float*)d_in[4];
    const float* b2 = (const float*)d_in[5];
    float*       out = (float*)d_out;

    static cudaStream_t s1 = nullptr;
    static cudaEvent_t  ev_fork = nullptr, ev_join = nullptr;
    if (!s1) {
        cudaStreamCreateWithFlags(&s1, cudaStreamNonBlocking);
        cudaEventCreateWithFlags(&ev_fork, cudaEventDisableTiming);
        cudaEventCreateWithFlags(&ev_join, cudaEventDisableTiming);
    }

    const int E4B = (EE / 4 + 255) / 256;   // 3125
    const int GB  = (NN / 16 + 3) / 4;      // 1563 blocks, 4 warps x 16 rows

    // critical path: CSR build
    k_hist<<<E4B, 256>>>(ei);

    // fork immediately after hist: gemm1 reads only x, W1, g_fill (complete).
    // It overlaps BOTH k_scan and k_scatter on the side stream.
    cudaEventRecord(ev_fork, 0);
    cudaStreamWaitEvent(s1, ev_fork, 0);
    k_gemm1<<<GB, 128, 0, s1>>>(x, W1);
    cudaEventRecord(ev_join, s1);

    k_scan<<<SCAN_B, SCAN_T>>>();           // rowptr + dinv (g_fill left intact)
    k_scatter<<<E4B, 256>>>(ei);            // also clears g_flags

    cudaStreamWaitEvent(0, ev_join, 0);
    k_agg1<<<(NN + 7) / 8, 256>>>(b1);
    k_agg2<<<(NN + 7) / 8, 256>>>(W2, b2, out);   // also re-zeroes g_fill
}